// round 3
// baseline (speedup 1.0000x reference)
#include <cuda_runtime.h>
#include <math.h>

#define SEQ     4096
#define DIM     1280
#define NHEAD   16
#define HDIM    80
#define HIDDEN  5120
#define QKVDIM  3840
#define EPS     1e-6f

// ---------------- scratch (allocation-free) ----------------
__device__ float g_xln [SEQ * DIM];     // LN output (reused for ln1 and ln2)
__device__ float g_qkv [SEQ * QKVDIM];  // qkv projections (rope applied in place)
__device__ float g_attn[SEQ * DIM];     // attention output
__device__ float g_res [SEQ * DIM];     // h after first residual
__device__ float g_fc1 [SEQ * HIDDEN];  // gelu(fc1) output

// ---------------- LayerNorm: one block per row ----------------
__global__ void __launch_bounds__(256) ln_kernel(const float* __restrict__ x,
                                                 const float* __restrict__ g,
                                                 const float* __restrict__ b,
                                                 float* __restrict__ y)
{
    int row = blockIdx.x;
    const float* xr = x + (size_t)row * DIM;
    float* yr = y + (size_t)row * DIM;

    float v[5];
    float s = 0.f, s2 = 0.f;
#pragma unroll
    for (int j = 0; j < 5; j++) {
        int i = threadIdx.x + j * 256;
        float t = xr[i];
        v[j] = t; s += t; s2 += t * t;
    }
#pragma unroll
    for (int off = 16; off > 0; off >>= 1) {
        s  += __shfl_xor_sync(0xffffffffu, s,  off);
        s2 += __shfl_xor_sync(0xffffffffu, s2, off);
    }
    __shared__ float sh[16];
    int w = threadIdx.x >> 5, ln = threadIdx.x & 31;
    if (ln == 0) { sh[w] = s; sh[8 + w] = s2; }
    __syncthreads();
    if (threadIdx.x == 0) {
        float ts = 0.f, ts2 = 0.f;
#pragma unroll
        for (int i = 0; i < 8; i++) { ts += sh[i]; ts2 += sh[8 + i]; }
        float mean = ts * (1.f / DIM);
        float var  = ts2 * (1.f / DIM) - mean * mean;
        sh[0] = mean;
        sh[1] = rsqrtf(var + EPS);
    }
    __syncthreads();
    float mean = sh[0], rstd = sh[1];
#pragma unroll
    for (int j = 0; j < 5; j++) {
        int i = threadIdx.x + j * 256;
        yr[i] = (v[j] - mean) * rstd * g[i] + b[i];
    }
}

// ---------------- RoPE: one thread per rotation pair (q and k) ----------------
__global__ void rope_kernel(float* __restrict__ qkv, const float* __restrict__ freqs)
{
    int idx = blockIdx.x * blockDim.x + threadIdx.x;
    if (idx >= SEQ * NHEAD * 40) return;
    int i = idx % 40;                 // pair index d in [0,40)
    int h = (idx / 40) % NHEAD;
    int n = idx / (40 * NHEAD);

    float f1 = freqs[n * 40 + (i >> 1)];
    float f2 = freqs[n * 40 + 20 + (i >> 1)];
    float c1 = cosf(f1), s1 = sinf(f1);
    float c2 = cosf(f2), s2 = sinf(f2);

    size_t base = (size_t)n * QKVDIM + h * HDIM;
    // q
    {
        float* q = qkv + base;
        float qa = q[i], qb = q[i + 40];
        q[i]      = qa * c1 - qb * s1;
        q[i + 40] = qb * c2 + qa * s2;
    }
    // k
    {
        float* k = qkv + base + DIM;
        float ka = k[i], kb = k[i + 40];
        k[i]      = ka * c1 - kb * s1;
        k[i + 40] = kb * c2 + ka * s2;
    }
}

// ---------------- Generic SGEMM: C = A[M,K] @ B[K,N] + bias (+act)(+residual) ----------------
// 128x128 block, BK=8, 256 threads, 8x8 per-thread in 4+4 split (conflict-free)
template<int ACT, int RES>
__global__ void __launch_bounds__(256) gemm_kernel(const float* __restrict__ A,
                                                   const float* __restrict__ B,
                                                   const float* __restrict__ bias,
                                                   const float* __restrict__ R,
                                                   float* __restrict__ C,
                                                   int M, int N, int K)
{
    __shared__ float As[8][128];
    __shared__ float Bs[8][128];

    const int t  = threadIdx.x;
    const int tx = t & 15, ty = t >> 4;
    const int m0 = blockIdx.y * 128, n0 = blockIdx.x * 128;

    float acc[8][8];
#pragma unroll
    for (int i = 0; i < 8; i++)
#pragma unroll
        for (int j = 0; j < 8; j++) acc[i][j] = 0.f;

    const int arow = t >> 1;
    const int akq  = (t & 1) << 2;
    const int brow = t >> 5;
    const int bcol = (t & 31) << 2;
    const float* Ap = A + (size_t)(m0 + arow) * K + akq;
    const float* Bp = B + (size_t)brow * N + n0 + bcol;

    for (int k0 = 0; k0 < K; k0 += 8) {
        float4 av = *(const float4*)(Ap + k0);
        float4 bv = *(const float4*)(Bp + (size_t)k0 * N);
        As[akq + 0][arow] = av.x;
        As[akq + 1][arow] = av.y;
        As[akq + 2][arow] = av.z;
        As[akq + 3][arow] = av.w;
        *(float4*)&Bs[brow][bcol] = bv;
        __syncthreads();
#pragma unroll
        for (int k = 0; k < 8; k++) {
            float a[8], bb[8];
            *(float4*)(a)      = *(const float4*)&As[k][ty << 2];
            *(float4*)(a + 4)  = *(const float4*)&As[k][64 + (ty << 2)];
            *(float4*)(bb)     = *(const float4*)&Bs[k][tx << 2];
            *(float4*)(bb + 4) = *(const float4*)&Bs[k][64 + (tx << 2)];
#pragma unroll
            for (int i = 0; i < 8; i++)
#pragma unroll
                for (int j = 0; j < 8; j++)
                    acc[i][j] = fmaf(a[i], bb[j], acc[i][j]);
        }
        __syncthreads();
    }

    int rows[8], cols[8];
#pragma unroll
    for (int i = 0; i < 4; i++) {
        rows[i]     = m0 + (ty << 2) + i;
        rows[i + 4] = m0 + 64 + (ty << 2) + i;
        cols[i]     = n0 + (tx << 2) + i;
        cols[i + 4] = n0 + 64 + (tx << 2) + i;
    }
    float bv8[8];
#pragma unroll
    for (int j = 0; j < 8; j++) bv8[j] = bias[cols[j]];
#pragma unroll
    for (int i = 0; i < 8; i++) {
        size_t roff = (size_t)rows[i] * N;
#pragma unroll
        for (int j = 0; j < 8; j++) {
            float v = acc[i][j] + bv8[j];
            if (ACT) v = v / (1.f + __expf(-1.702f * v));   // quickGELU
            if (RES) v += R[roff + cols[j]];
            C[roff + cols[j]] = v;
        }
    }
}

// ---------------- Flash attention: block per (q-tile 64, head, segment) ----------------
#define ASTRIDE 84   // smem row stride (floats) — de-conflicts 16-lane K fragment reads
#define ATT_SMEM_FLOATS (3 * 64 * ASTRIDE + 64 * 64 + 3 * 64)

__global__ void __launch_bounds__(256) attn_kernel(const float* __restrict__ qkv,
                                                   const int* __restrict__ cu,
                                                   float* __restrict__ out)
{
    extern __shared__ float sm[];
    float* Qs  = sm;                       // 64 x ASTRIDE
    float* Ks  = Qs + 64 * ASTRIDE;
    float* Vs  = Ks + 64 * ASTRIDE;
    float* Ps  = Vs + 64 * ASTRIDE;        // 64 x 64
    float* m_s = Ps + 64 * 64;
    float* l_s = m_s + 64;
    float* a_s = l_s + 64;

    const int t    = threadIdx.x;
    const int seg  = blockIdx.z;
    const int head = blockIdx.y;
    const int s0   = cu[seg];
    const int len  = cu[seg + 1] - s0;
    const int q0   = blockIdx.x * 64;
    if (q0 >= len) return;

    const float scale = 0.1118033988749895f;   // 1/sqrt(80)
    const size_t hoff = (size_t)head * HDIM;

    // load Q tile (pre-scaled)
    for (int i = t; i < 64 * 20; i += 256) {
        int r = i / 20, kq = (i % 20) * 4;
        float4 v = *(const float4*)(qkv + (size_t)(s0 + q0 + r) * QKVDIM + hoff + kq);
        v.x *= scale; v.y *= scale; v.z *= scale; v.w *= scale;
        *(float4*)&Qs[r * ASTRIDE + kq] = v;
    }
    if (t < 64) { m_s[t] = -3.0e38f; l_s[t] = 0.f; }

    float oacc[20];
#pragma unroll
    for (int c = 0; c < 20; c++) oacc[c] = 0.f;

    const int i4 = t >> 4;          // S-phase: rows i4 + 16a
    const int j4 = t & 15;          //          cols j4 + 16b
    const int r_pv = t >> 2;        // PV-phase: row, 4 threads per row
    const int c_pv = (t & 3) * 20;  //           20 output cols each

    const int ntiles = len >> 6;
    for (int kt = 0; kt < ntiles; kt++) {
        __syncthreads();            // protect Ks/Vs from previous PV reads
        for (int i = t; i < 64 * 20; i += 256) {
            int r = i / 20, kq = (i % 20) * 4;
            const float* gp = qkv + (size_t)(s0 + kt * 64 + r) * QKVDIM + hoff + kq;
            *(float4*)&Ks[r * ASTRIDE + kq] = *(const float4*)(gp + DIM);
            *(float4*)&Vs[r * ASTRIDE + kq] = *(const float4*)(gp + 2 * DIM);
        }
        __syncthreads();

        // S tile: 4x4 fragment per thread, vectorized over k
        float s[4][4];
#pragma unroll
        for (int a = 0; a < 4; a++)
#pragma unroll
            for (int b = 0; b < 4; b++) s[a][b] = 0.f;
#pragma unroll 5
        for (int kq = 0; kq < 20; kq++) {
            float4 qa[4], kb[4];
#pragma unroll
            for (int a = 0; a < 4; a++)
                qa[a] = *(const float4*)&Qs[(i4 + 16 * a) * ASTRIDE + kq * 4];
#pragma unroll
            for (int b = 0; b < 4; b++)
                kb[b] = *(const float4*)&Ks[(j4 + 16 * b) * ASTRIDE + kq * 4];
#pragma unroll
            for (int a = 0; a < 4; a++)
#pragma unroll
                for (int b = 0; b < 4; b++)
                    s[a][b] += qa[a].x * kb[b].x + qa[a].y * kb[b].y +
                               qa[a].z * kb[b].z + qa[a].w * kb[b].w;
        }

        // online softmax, per row (16 lanes j4 own one row together)
#pragma unroll
        for (int a = 0; a < 4; a++) {
            int r = i4 + 16 * a;
            float tm = fmaxf(fmaxf(s[a][0], s[a][1]), fmaxf(s[a][2], s[a][3]));
#pragma unroll
            for (int off = 1; off < 16; off <<= 1)
                tm = fmaxf(tm, __shfl_xor_sync(0xffffffffu, tm, off));
            float m_old = m_s[r];
            float m_new = fmaxf(m_old, tm);
            float p[4];
            float ts = 0.f;
#pragma unroll
            for (int b = 0; b < 4; b++) { p[b] = __expf(s[a][b] - m_new); ts += p[b]; }
#pragma unroll
            for (int off = 1; off < 16; off <<= 1)
                ts += __shfl_xor_sync(0xffffffffu, ts, off);
            // full-warp shuffles above guarantee every lane has read m_s[r]/l state
#pragma unroll
            for (int b = 0; b < 4; b++) Ps[r * 64 + j4 + 16 * b] = p[b];
            if (j4 == 0) {
                float al = __expf(m_old - m_new);
                a_s[r] = al;
                m_s[r] = m_new;
                l_s[r] = l_s[r] * al + ts;
            }
        }
        __syncthreads();

        // O += P @ V  (thread: one row, 20 cols)
        float alpha = a_s[r_pv];
#pragma unroll
        for (int c = 0; c < 20; c++) oacc[c] *= alpha;
        for (int k = 0; k < 64; k++) {
            float p = Ps[r_pv * 64 + k];
            const float* vp = &Vs[k * ASTRIDE + c_pv];
#pragma unroll
            for (int c = 0; c < 20; c++) oacc[c] += p * vp[c];
        }
    }

    float invl = 1.f / l_s[r_pv];
    float* op = out + (size_t)(s0 + q0 + r_pv) * DIM + hoff + c_pv;
#pragma unroll
    for (int c = 0; c < 20; c++) op[c] = oacc[c] * invl;
}

// ---------------- launch ----------------
extern "C" void kernel_launch(void* const* d_in, const int* in_sizes, int n_in,
                              void* d_out, int out_size)
{
    const float* hidden = (const float*)d_in[0];
    const float* rope   = (const float*)d_in[1];
    const int*   cu     = (const int*)  d_in[2];
    const float* w_qkv  = (const float*)d_in[3];
    const float* b_qkv  = (const float*)d_in[4];
    const float* w_proj = (const float*)d_in[5];
    const float* b_proj = (const float*)d_in[6];
    const float* w_fc1  = (const float*)d_in[7];
    const float* b_fc1  = (const float*)d_in[8];
    const float* w_fc2  = (const float*)d_in[9];
    const float* b_fc2  = (const float*)d_in[10];
    const float* ln1s   = (const float*)d_in[11];
    const float* ln1b   = (const float*)d_in[12];
    const float* ln2s   = (const float*)d_in[13];
    const float* ln2b   = (const float*)d_in[14];
    float* out = (float*)d_out;

    float *xln, *qkvp, *attnp, *resp, *fc1p;
    cudaGetSymbolAddress((void**)&xln,   g_xln);
    cudaGetSymbolAddress((void**)&qkvp,  g_qkv);
    cudaGetSymbolAddress((void**)&attnp, g_attn);
    cudaGetSymbolAddress((void**)&resp,  g_res);
    cudaGetSymbolAddress((void**)&fc1p,  g_fc1);

    const int att_smem = ATT_SMEM_FLOATS * (int)sizeof(float);
    cudaFuncSetAttribute(attn_kernel, cudaFuncAttributeMaxDynamicSharedMemorySize, att_smem);

    // 1) LN1
    ln_kernel<<<SEQ, 256>>>(hidden, ln1s, ln1b, xln);
    // 2) QKV projection
    gemm_kernel<0, 0><<<dim3(QKVDIM / 128, SEQ / 128), 256>>>(
        xln, w_qkv, b_qkv, nullptr, qkvp, SEQ, QKVDIM, DIM);
    // 3) RoPE (in place on q,k)
    rope_kernel<<<(SEQ * NHEAD * 40 + 255) / 256, 256>>>(qkvp, rope);
    // 4) block-diagonal attention
    attn_kernel<<<dim3(16, NHEAD, 4), 256, att_smem>>>(qkvp, cu, attnp);
    // 5) output projection + residual
    gemm_kernel<0, 1><<<dim3(DIM / 128, SEQ / 128), 256>>>(
        attnp, w_proj, b_proj, hidden, resp, SEQ, DIM, DIM);
    // 6) LN2
    ln_kernel<<<SEQ, 256>>>(resp, ln2s, ln2b, xln);
    // 7) FC1 + quickGELU
    gemm_kernel<1, 0><<<dim3(HIDDEN / 128, SEQ / 128), 256>>>(
        xln, w_fc1, b_fc1, nullptr, fc1p, SEQ, HIDDEN, DIM);
    // 8) FC2 + residual -> out
    gemm_kernel<0, 1><<<dim3(DIM / 128, SEQ / 128), 256>>>(
        fc1p, w_fc2, b_fc2, resp, out, SEQ, DIM, HIDDEN);
}

// round 7
// speedup vs baseline: 2.0641x; 2.0641x over previous
#include <cuda_runtime.h>
#include <math.h>
#include <stdint.h>

#define SEQ     4096
#define DIM     1280
#define NHEAD   16
#define HDIM    80
#define HIDDEN  5120
#define QKVDIM  3840
#define EPS     1e-6f

// ---------------- scratch (allocation-free) ----------------
__device__ float g_xln [SEQ * DIM];     // LN output (reused for ln1 and ln2)
__device__ float g_qkv [SEQ * QKVDIM];  // qkv projections (rope applied in place)
__device__ float g_attn[SEQ * DIM];     // attention output
__device__ float g_res [SEQ * DIM];     // h after first residual
__device__ float g_fc1 [SEQ * HIDDEN];  // gelu(fc1) output

// ---------------- LayerNorm: one block per row ----------------
__global__ void __launch_bounds__(256) ln_kernel(const float* __restrict__ x,
                                                 const float* __restrict__ g,
                                                 const float* __restrict__ b,
                                                 float* __restrict__ y)
{
    int row = blockIdx.x;
    const float* xr = x + (size_t)row * DIM;
    float* yr = y + (size_t)row * DIM;

    float v[5];
    float s = 0.f, s2 = 0.f;
#pragma unroll
    for (int j = 0; j < 5; j++) {
        int i = threadIdx.x + j * 256;
        float t = xr[i];
        v[j] = t; s += t; s2 += t * t;
    }
#pragma unroll
    for (int off = 16; off > 0; off >>= 1) {
        s  += __shfl_xor_sync(0xffffffffu, s,  off);
        s2 += __shfl_xor_sync(0xffffffffu, s2, off);
    }
    __shared__ float sh[16];
    int w = threadIdx.x >> 5, ln = threadIdx.x & 31;
    if (ln == 0) { sh[w] = s; sh[8 + w] = s2; }
    __syncthreads();
    if (threadIdx.x == 0) {
        float ts = 0.f, ts2 = 0.f;
#pragma unroll
        for (int i = 0; i < 8; i++) { ts += sh[i]; ts2 += sh[8 + i]; }
        float mean = ts * (1.f / DIM);
        float var  = ts2 * (1.f / DIM) - mean * mean;
        sh[0] = mean;
        sh[1] = rsqrtf(var + EPS);
    }
    __syncthreads();
    float mean = sh[0], rstd = sh[1];
#pragma unroll
    for (int j = 0; j < 5; j++) {
        int i = threadIdx.x + j * 256;
        yr[i] = (v[j] - mean) * rstd * g[i] + b[i];
    }
}

// ---------------- RoPE: one thread per rotation pair (q and k) ----------------
__global__ void rope_kernel(float* __restrict__ qkv, const float* __restrict__ freqs)
{
    int idx = blockIdx.x * blockDim.x + threadIdx.x;
    if (idx >= SEQ * NHEAD * 40) return;
    int i = idx % 40;                 // pair index d in [0,40)
    int h = (idx / 40) % NHEAD;
    int n = idx / (40 * NHEAD);

    float f1 = freqs[n * 40 + (i >> 1)];
    float f2 = freqs[n * 40 + 20 + (i >> 1)];
    float c1 = cosf(f1), s1 = sinf(f1);
    float c2 = cosf(f2), s2 = sinf(f2);

    size_t base = (size_t)n * QKVDIM + h * HDIM;
    {
        float* q = qkv + base;
        float qa = q[i], qb = q[i + 40];
        q[i]      = qa * c1 - qb * s1;
        q[i + 40] = qb * c2 + qa * s2;
    }
    {
        float* k = qkv + base + DIM;
        float ka = k[i], kb = k[i + 40];
        k[i]      = ka * c1 - kb * s1;
        k[i + 40] = kb * c2 + ka * s2;
    }
}

// ---------------- TF32 tensor-core GEMM ----------------
// C[M,N] = A[M,K] @ B[K,N] + bias (+quickGELU)(+residual)
// 128x128 block tile, BK=16, 256 threads (8 warps, 2x4), warp tile 64x32,
// mma.sync.m16n8k8 tf32, double-buffered smem with register prefetch.

__device__ __forceinline__ uint32_t tf32_of(float x) {
    uint32_t y;
    asm("cvt.rna.tf32.f32 %0, %1;" : "=r"(y) : "f"(x));
    return y;
}

__device__ __forceinline__ void mma_tf32(float* c, const uint32_t* a, const uint32_t* b) {
    asm volatile(
        "mma.sync.aligned.m16n8k8.row.col.f32.tf32.tf32.f32 "
        "{%0,%1,%2,%3}, {%4,%5,%6,%7}, {%8,%9}, {%0,%1,%2,%3};"
        : "+f"(c[0]), "+f"(c[1]), "+f"(c[2]), "+f"(c[3])
        : "r"(a[0]), "r"(a[1]), "r"(a[2]), "r"(a[3]),
          "r"(b[0]), "r"(b[1]));
}

template<int ACT, int RES>
__global__ void __launch_bounds__(256) gemm_tc(const float* __restrict__ A,
                                               const float* __restrict__ B,
                                               const float* __restrict__ bias,
                                               const float* __restrict__ R,
                                               float* __restrict__ C,
                                               int M, int N, int K)
{
    // stride 20 -> A fragment gathers conflict-free; stride 136 -> B conflict-free
    __shared__ uint32_t As[2][128][20];
    __shared__ uint32_t Bs[2][16][136];

    const int t    = threadIdx.x;
    const int lane = t & 31;
    const int warp = t >> 5;
    const int wr   = warp & 1;        // warp row (2)
    const int wc   = warp >> 1;       // warp col (4)
    const int m0   = blockIdx.y * 128;
    const int n0   = blockIdx.x * 128;

    // staging assignment
    const int a_row = t >> 2;                 // 0..63  (plus +64 for second half)
    const int a_kq  = (t & 3) << 2;           // 0,4,8,12
    const int b_kr  = t >> 5;                 // 0..7   (plus +8)
    const int b_nq  = (t & 31) << 2;          // 0..124

    const float* Ap0 = A + (size_t)(m0 + a_row)      * K + a_kq;
    const float* Ap1 = A + (size_t)(m0 + a_row + 64) * K + a_kq;
    const float* Bp0 = B + (size_t)(b_kr)     * N + n0 + b_nq;
    const float* Bp1 = B + (size_t)(b_kr + 8) * N + n0 + b_nq;

    float acc[4][4][4];
#pragma unroll
    for (int i = 0; i < 4; i++)
#pragma unroll
        for (int j = 0; j < 4; j++)
#pragma unroll
            for (int q = 0; q < 4; q++) acc[i][j][q] = 0.f;

    const int fr = lane >> 2;   // 0..7
    const int fc = lane & 3;    // 0..3

    // ---- prologue: stage tile 0 ----
    {
        float4 av0 = *(const float4*)(Ap0);
        float4 av1 = *(const float4*)(Ap1);
        float4 bv0 = *(const float4*)(Bp0);
        float4 bv1 = *(const float4*)(Bp1);
        uint4 u;
        u.x = tf32_of(av0.x); u.y = tf32_of(av0.y); u.z = tf32_of(av0.z); u.w = tf32_of(av0.w);
        *(uint4*)&As[0][a_row][a_kq] = u;
        u.x = tf32_of(av1.x); u.y = tf32_of(av1.y); u.z = tf32_of(av1.z); u.w = tf32_of(av1.w);
        *(uint4*)&As[0][a_row + 64][a_kq] = u;
        u.x = tf32_of(bv0.x); u.y = tf32_of(bv0.y); u.z = tf32_of(bv0.z); u.w = tf32_of(bv0.w);
        *(uint4*)&Bs[0][b_kr][b_nq] = u;
        u.x = tf32_of(bv1.x); u.y = tf32_of(bv1.y); u.z = tf32_of(bv1.z); u.w = tf32_of(bv1.w);
        *(uint4*)&Bs[0][b_kr + 8][b_nq] = u;
    }
    __syncthreads();

    int buf = 0;
    for (int k0 = 16; k0 <= K - 16; k0 += 16) {
        // prefetch next tile to registers
        float4 av0 = *(const float4*)(Ap0 + k0);
        float4 av1 = *(const float4*)(Ap1 + k0);
        float4 bv0 = *(const float4*)(Bp0 + (size_t)k0 * N);
        float4 bv1 = *(const float4*)(Bp1 + (size_t)k0 * N);

        // compute current buffer
#pragma unroll
        for (int ks = 0; ks < 2; ks++) {
            const int kb = ks * 8;
            uint32_t af[4][4], bf[4][2];
#pragma unroll
            for (int i = 0; i < 4; i++) {
                int mr = wr * 64 + i * 16;
                af[i][0] = As[buf][mr + fr    ][kb + fc];
                af[i][1] = As[buf][mr + fr + 8][kb + fc];
                af[i][2] = As[buf][mr + fr    ][kb + fc + 4];
                af[i][3] = As[buf][mr + fr + 8][kb + fc + 4];
            }
#pragma unroll
            for (int j = 0; j < 4; j++) {
                int nc = wc * 32 + j * 8 + fr;
                bf[j][0] = Bs[buf][kb + fc    ][nc];
                bf[j][1] = Bs[buf][kb + fc + 4][nc];
            }
#pragma unroll
            for (int i = 0; i < 4; i++)
#pragma unroll
                for (int j = 0; j < 4; j++)
                    mma_tf32(acc[i][j], af[i], bf[j]);
        }

        // stage prefetched tile into the other buffer
        {
            int nb = buf ^ 1;
            uint4 u;
            u.x = tf32_of(av0.x); u.y = tf32_of(av0.y); u.z = tf32_of(av0.z); u.w = tf32_of(av0.w);
            *(uint4*)&As[nb][a_row][a_kq] = u;
            u.x = tf32_of(av1.x); u.y = tf32_of(av1.y); u.z = tf32_of(av1.z); u.w = tf32_of(av1.w);
            *(uint4*)&As[nb][a_row + 64][a_kq] = u;
            u.x = tf32_of(bv0.x); u.y = tf32_of(bv0.y); u.z = tf32_of(bv0.z); u.w = tf32_of(bv0.w);
            *(uint4*)&Bs[nb][b_kr][b_nq] = u;
            u.x = tf32_of(bv1.x); u.y = tf32_of(bv1.y); u.z = tf32_of(bv1.z); u.w = tf32_of(bv1.w);
            *(uint4*)&Bs[nb][b_kr + 8][b_nq] = u;
        }
        __syncthreads();
        buf ^= 1;
    }

    // final tile compute
#pragma unroll
    for (int ks = 0; ks < 2; ks++) {
        const int kb = ks * 8;
        uint32_t af[4][4], bf[4][2];
#pragma unroll
        for (int i = 0; i < 4; i++) {
            int mr = wr * 64 + i * 16;
            af[i][0] = As[buf][mr + fr    ][kb + fc];
            af[i][1] = As[buf][mr + fr + 8][kb + fc];
            af[i][2] = As[buf][mr + fr    ][kb + fc + 4];
            af[i][3] = As[buf][mr + fr + 8][kb + fc + 4];
        }
#pragma unroll
        for (int j = 0; j < 4; j++) {
            int nc = wc * 32 + j * 8 + fr;
            bf[j][0] = Bs[buf][kb + fc    ][nc];
            bf[j][1] = Bs[buf][kb + fc + 4][nc];
        }
#pragma unroll
        for (int i = 0; i < 4; i++)
#pragma unroll
            for (int j = 0; j < 4; j++)
                mma_tf32(acc[i][j], af[i], bf[j]);
    }

    // ---- epilogue ----
    const int c2 = fc * 2;
#pragma unroll
    for (int i = 0; i < 4; i++) {
        int row0 = m0 + wr * 64 + i * 16 + fr;
        int row1 = row0 + 8;
#pragma unroll
        for (int j = 0; j < 4; j++) {
            int col = n0 + wc * 32 + j * 8 + c2;
            float bx = bias[col], by = bias[col + 1];
            float v0 = acc[i][j][0] + bx;
            float v1 = acc[i][j][1] + by;
            float v2 = acc[i][j][2] + bx;
            float v3 = acc[i][j][3] + by;
            if (ACT) {
                v0 = v0 / (1.f + __expf(-1.702f * v0));
                v1 = v1 / (1.f + __expf(-1.702f * v1));
                v2 = v2 / (1.f + __expf(-1.702f * v2));
                v3 = v3 / (1.f + __expf(-1.702f * v3));
            }
            if (RES) {
                float2 r0 = *(const float2*)&R[(size_t)row0 * N + col];
                float2 r1 = *(const float2*)&R[(size_t)row1 * N + col];
                v0 += r0.x; v1 += r0.y; v2 += r1.x; v3 += r1.y;
            }
            float2 o0 = make_float2(v0, v1);
            float2 o1 = make_float2(v2, v3);
            *(float2*)&C[(size_t)row0 * N + col] = o0;
            *(float2*)&C[(size_t)row1 * N + col] = o1;
        }
    }
}

// ---------------- Flash attention: block per (q-tile 64, head, segment) ----------------
#define ASTRIDE 84   // smem row stride (floats) — de-conflicts 16-lane K fragment reads
#define ATT_SMEM_FLOATS (3 * 64 * ASTRIDE + 64 * 64 + 3 * 64)

__global__ void __launch_bounds__(256) attn_kernel(const float* __restrict__ qkv,
                                                   const int* __restrict__ cu,
                                                   float* __restrict__ out)
{
    extern __shared__ float sm[];
    float* Qs  = sm;                       // 64 x ASTRIDE
    float* Ks  = Qs + 64 * ASTRIDE;
    float* Vs  = Ks + 64 * ASTRIDE;
    float* Ps  = Vs + 64 * ASTRIDE;        // 64 x 64
    float* m_s = Ps + 64 * 64;
    float* l_s = m_s + 64;
    float* a_s = l_s + 64;

    const int t    = threadIdx.x;
    const int seg  = blockIdx.z;
    const int head = blockIdx.y;
    const int s0   = cu[seg];
    const int len  = cu[seg + 1] - s0;
    const int q0   = blockIdx.x * 64;
    if (q0 >= len) return;

    const float scale = 0.1118033988749895f;   // 1/sqrt(80)
    const size_t hoff = (size_t)head * HDIM;

    for (int i = t; i < 64 * 20; i += 256) {
        int r = i / 20, kq = (i % 20) * 4;
        float4 v = *(const float4*)(qkv + (size_t)(s0 + q0 + r) * QKVDIM + hoff + kq);
        v.x *= scale; v.y *= scale; v.z *= scale; v.w *= scale;
        *(float4*)&Qs[r * ASTRIDE + kq] = v;
    }
    if (t < 64) { m_s[t] = -3.0e38f; l_s[t] = 0.f; }

    float oacc[20];
#pragma unroll
    for (int c = 0; c < 20; c++) oacc[c] = 0.f;

    const int i4 = t >> 4;
    const int j4 = t & 15;
    const int r_pv = t >> 2;
    const int c_pv = (t & 3) * 20;

    const int ntiles = len >> 6;
    for (int kt = 0; kt < ntiles; kt++) {
        __syncthreads();
        for (int i = t; i < 64 * 20; i += 256) {
            int r = i / 20, kq = (i % 20) * 4;
            const float* gp = qkv + (size_t)(s0 + kt * 64 + r) * QKVDIM + hoff + kq;
            *(float4*)&Ks[r * ASTRIDE + kq] = *(const float4*)(gp + DIM);
            *(float4*)&Vs[r * ASTRIDE + kq] = *(const float4*)(gp + 2 * DIM);
        }
        __syncthreads();

        float s[4][4];
#pragma unroll
        for (int a = 0; a < 4; a++)
#pragma unroll
            for (int b = 0; b < 4; b++) s[a][b] = 0.f;
#pragma unroll 5
        for (int kq = 0; kq < 20; kq++) {
            float4 qa[4], kb[4];
#pragma unroll
            for (int a = 0; a < 4; a++)
                qa[a] = *(const float4*)&Qs[(i4 + 16 * a) * ASTRIDE + kq * 4];
#pragma unroll
            for (int b = 0; b < 4; b++)
                kb[b] = *(const float4*)&Ks[(j4 + 16 * b) * ASTRIDE + kq * 4];
#pragma unroll
            for (int a = 0; a < 4; a++)
#pragma unroll
                for (int b = 0; b < 4; b++)
                    s[a][b] += qa[a].x * kb[b].x + qa[a].y * kb[b].y +
                               qa[a].z * kb[b].z + qa[a].w * kb[b].w;
        }

#pragma unroll
        for (int a = 0; a < 4; a++) {
            int r = i4 + 16 * a;
            float tm = fmaxf(fmaxf(s[a][0], s[a][1]), fmaxf(s[a][2], s[a][3]));
#pragma unroll
            for (int off = 1; off < 16; off <<= 1)
                tm = fmaxf(tm, __shfl_xor_sync(0xffffffffu, tm, off));
            float m_old = m_s[r];
            float m_new = fmaxf(m_old, tm);
            float p[4];
            float ts = 0.f;
#pragma unroll
            for (int b = 0; b < 4; b++) { p[b] = __expf(s[a][b] - m_new); ts += p[b]; }
#pragma unroll
            for (int off = 1; off < 16; off <<= 1)
                ts += __shfl_xor_sync(0xffffffffu, ts, off);
#pragma unroll
            for (int b = 0; b < 4; b++) Ps[r * 64 + j4 + 16 * b] = p[b];
            if (j4 == 0) {
                float al = __expf(m_old - m_new);
                a_s[r] = al;
                m_s[r] = m_new;
                l_s[r] = l_s[r] * al + ts;
            }
        }
        __syncthreads();

        float alpha = a_s[r_pv];
#pragma unroll
        for (int c = 0; c < 20; c++) oacc[c] *= alpha;
        for (int k = 0; k < 64; k++) {
            float p = Ps[r_pv * 64 + k];
            const float* vp = &Vs[k * ASTRIDE + c_pv];
#pragma unroll
            for (int c = 0; c < 20; c++) oacc[c] += p * vp[c];
        }
    }

    float invl = 1.f / l_s[r_pv];
    float* op = out + (size_t)(s0 + q0 + r_pv) * DIM + hoff + c_pv;
#pragma unroll
    for (int c = 0; c < 20; c++) op[c] = oacc[c] * invl;
}

// ---------------- launch ----------------
extern "C" void kernel_launch(void* const* d_in, const int* in_sizes, int n_in,
                              void* d_out, int out_size)
{
    const float* hidden = (const float*)d_in[0];
    const float* rope   = (const float*)d_in[1];
    const int*   cu     = (const int*)  d_in[2];
    const float* w_qkv  = (const float*)d_in[3];
    const float* b_qkv  = (const float*)d_in[4];
    const float* w_proj = (const float*)d_in[5];
    const float* b_proj = (const float*)d_in[6];
    const float* w_fc1  = (const float*)d_in[7];
    const float* b_fc1  = (const float*)d_in[8];
    const float* w_fc2  = (const float*)d_in[9];
    const float* b_fc2  = (const float*)d_in[10];
    const float* ln1s   = (const float*)d_in[11];
    const float* ln1b   = (const float*)d_in[12];
    const float* ln2s   = (const float*)d_in[13];
    const float* ln2b   = (const float*)d_in[14];
    float* out = (float*)d_out;

    float *xln, *qkvp, *attnp, *resp, *fc1p;
    cudaGetSymbolAddress((void**)&xln,   g_xln);
    cudaGetSymbolAddress((void**)&qkvp,  g_qkv);
    cudaGetSymbolAddress((void**)&attnp, g_attn);
    cudaGetSymbolAddress((void**)&resp,  g_res);
    cudaGetSymbolAddress((void**)&fc1p,  g_fc1);

    const int att_smem = ATT_SMEM_FLOATS * (int)sizeof(float);
    cudaFuncSetAttribute(attn_kernel, cudaFuncAttributeMaxDynamicSharedMemorySize, att_smem);

    // 1) LN1
    ln_kernel<<<SEQ, 256>>>(hidden, ln1s, ln1b, xln);
    // 2) QKV projection (TF32 MMA)
    gemm_tc<0, 0><<<dim3(QKVDIM / 128, SEQ / 128), 256>>>(
        xln, w_qkv, b_qkv, nullptr, qkvp, SEQ, QKVDIM, DIM);
    // 3) RoPE (in place on q,k)
    rope_kernel<<<(SEQ * NHEAD * 40 + 255) / 256, 256>>>(qkvp, rope);
    // 4) block-diagonal attention
    attn_kernel<<<dim3(16, NHEAD, 4), 256, att_smem>>>(qkvp, cu, attnp);
    // 5) output projection + residual (TF32 MMA)
    gemm_tc<0, 1><<<dim3(DIM / 128, SEQ / 128), 256>>>(
        attnp, w_proj, b_proj, hidden, resp, SEQ, DIM, DIM);
    // 6) LN2
    ln_kernel<<<SEQ, 256>>>(resp, ln2s, ln2b, xln);
    // 7) FC1 + quickGELU (TF32 MMA)
    gemm_tc<1, 0><<<dim3(HIDDEN / 128, SEQ / 128), 256>>>(
        xln, w_fc1, b_fc1, nullptr, fc1p, SEQ, HIDDEN, DIM);
    // 8) FC2 + residual -> out (TF32 MMA)
    gemm_tc<0, 1><<<dim3(DIM / 128, SEQ / 128), 256>>>(
        fc1p, w_fc2, b_fc2, resp, out, SEQ, DIM, HIDDEN);
}